// round 7
// baseline (speedup 1.0000x reference)
#include <cuda_runtime.h>
#include <cstdint>

// GCN FeatureDiscriminator: B=256, V=512, F=256, O=2
// Single fused persistent-style kernel:
//  - global atomic work queue over A-chunks (4 rows, batch-major) -> streaming
//    pass is self-balancing and completes batches in staggered order
//  - per-batch completion counters; CTA c aggregates batch c as soon as it's
//    ready, interleaved with streaming, then resumes streaming
//  - all 304 CTAs resident (512 thr, occ 2) -> polling is deadlock-free

#define BATCH 256
#define BV 512
#define BF 256
#define NROWS (BATCH * BV)            // 131072
#define NTHREADS 512
#define NWARP 16
#define GRID 304
#define ROWS_PER_CHUNK 4
#define NCHUNKS (NROWS / ROWS_PER_CHUNK)      // 32768
#define CHUNKS_PER_BATCH (BV / ROWS_PER_CHUNK) // 128

__device__ unsigned g_bits[NROWS * 16];   // 8 MB: 512-bit mask per row
__device__ float    g_dinv[NROWS];
__device__ float2   g_sxw[NROWS];         // dinv[w] * (X[w,:] @ W)
__device__ int      g_next;               // chunk queue head
__device__ int      g_counter[BATCH];     // rows completed per batch

// ---------------------------------------------------------------------------
__global__ void init_kernel() {
    int t = threadIdx.x;
    if (t < BATCH) g_counter[t] = 0;
    if (t == BATCH) g_next = 0;
}

// ---------------------------------------------------------------------------
// Fused kernel.
// Bit convention: bits[row][4c+k] bit 'l'  <->  column w = 128*c + 4*l + k
// ---------------------------------------------------------------------------
__global__ __launch_bounds__(NTHREADS, 2)
void gcn_fused_kernel(const float* __restrict__ features,
                      const int*   __restrict__ graphs,
                      const float* __restrict__ conv_weight,   // [F,2]
                      const float* __restrict__ conv_bias,     // [2]
                      const float* __restrict__ lin_weight,    // [2v+o]
                      const float* __restrict__ lin_bias,
                      float* __restrict__ out)                 // [BATCH]
{
    __shared__ unsigned bits[BV][16];   // 32 KB (aggregation phase only)
    __shared__ float s0[BV];
    __shared__ float s1[BV];
    __shared__ float dinv_s[BV];
    __shared__ float lw_s[BV * 2];
    __shared__ float wpart[NWARP];

    const int c    = blockIdx.x;
    const int tid  = threadIdx.x;
    const int wid  = tid >> 5;
    const int lane = tid & 31;

    // per-lane fixed W slice: features f = 8*lane .. 8*lane+7
    float w0r[8], w1r[8];
    {
        const float2* cw2 = (const float2*)conv_weight;
        #pragma unroll
        for (int j = 0; j < 8; j++) {
            float2 w = __ldg(cw2 + 8 * lane + j);
            w0r[j] = w.x; w1r[j] = w.y;
        }
    }

    bool need_b = (c < BATCH);   // CTA-uniform at all times

    for (;;) {
        // ---------------- aggregation phase (once, when batch c is ready) ----
        if (need_b && *(volatile int*)&g_counter[c] >= BV) {
            // all warps observe the monotonic counter within one chunk and
            // converge here; no other __syncthreads exists on the A path.
            __syncthreads();
            __threadfence();   // acquire: producer stores -> visible

            // ---- stage (coalesced; mostly L2 hits: data just written) ----
            {
                const uint4* src = (const uint4*)g_bits + (size_t)c * (BV * 4);
                uint4* dst = (uint4*)bits;
                #pragma unroll
                for (int i = 0; i < 4; i++)
                    dst[tid + i * NTHREADS] = src[tid + i * NTHREADS];

                float2 xw = g_sxw[c * BV + tid];       // already dinv-scaled
                s0[tid] = xw.x;
                s1[tid] = xw.y;
                dinv_s[tid] = g_dinv[c * BV + tid];
                lw_s[tid]            = lin_weight[tid];
                lw_s[tid + NTHREADS] = lin_weight[tid + NTHREADS];
            }
            __syncthreads();

            // preload this lane's fixed 16 s pairs: w = 128*cc + 4*lane + k
            float r0[16], r1[16];
            #pragma unroll
            for (int cc = 0; cc < 4; cc++)
                #pragma unroll
                for (int k = 0; k < 4; k++) {
                    int w = 128 * cc + 4 * lane + k;
                    r0[4 * cc + k] = s0[w];
                    r1[4 * cc + k] = s1[w];
                }

            const float cb0 = conv_bias[0];
            const float cb1 = conv_bias[1];

            float part = 0.0f;
            #pragma unroll 2
            for (int r = 0; r < BV / NWARP; r++) {
                const int v = wid * (BV / NWARP) + r;
                float acc0 = 0.0f, acc1 = 0.0f;
                #pragma unroll
                for (int j = 0; j < 16; j++) {
                    unsigned m = bits[v][j];           // broadcast LDS
                    if ((m >> lane) & 1u) {
                        acc0 += r0[j];
                        acc1 += r1[j];
                    }
                }
                #pragma unroll
                for (int s = 16; s; s >>= 1) {
                    acc0 += __shfl_xor_sync(0xffffffffu, acc0, s);
                    acc1 += __shfl_xor_sync(0xffffffffu, acc1, s);
                }
                if (lane == 0) {
                    float d  = dinv_s[v];
                    float h0 = fmaxf(fmaf(d, acc0, cb0), 0.0f);
                    float h1 = fmaxf(fmaf(d, acc1, cb1), 0.0f);
                    part = fmaf(h0, lw_s[2 * v], part);
                    part = fmaf(h1, lw_s[2 * v + 1], part);
                }
            }
            if (lane == 0) wpart[wid] = part;
            __syncthreads();

            if (wid == 0) {
                float sdot = (lane < NWARP) ? wpart[lane] : 0.0f;
                #pragma unroll
                for (int sh = 8; sh; sh >>= 1)
                    sdot += __shfl_xor_sync(0xffffffffu, sdot, sh);
                if (lane == 0) {
                    float logit = sdot + lin_bias[0];
                    out[c] = 1.0f / (1.0f + expf(-logit));
                }
            }
            need_b = false;
            __syncthreads();
        }

        // ---------------- grab a streaming chunk -----------------------------
        int ch;
        if (lane == 0) ch = atomicAdd(&g_next, 1);
        ch = __shfl_sync(0xffffffffu, ch, 0);
        if (ch >= NCHUNKS) {
            if (!need_b) break;          // done (streamer, or B already run)
            __nanosleep(200);            // queue drained; waiting on batch c
            continue;
        }
        const int batch_of = ch / CHUNKS_PER_BATCH;   // chunks never straddle

        #pragma unroll 1
        for (int i = 0; i < ROWS_PER_CHUNK; i++) {
            const int row = ch * ROWS_PER_CHUNK + i;
            const int v = row & (BV - 1);
            const int4*   grow = (const int4*)graphs + (size_t)row * (BV / 4);
            const float4* frow = (const float4*)features + (size_t)row * (BF / 4);

            int4 x0 = __ldcs(grow + 0 * 32 + lane);
            int4 x1 = __ldcs(grow + 1 * 32 + lane);
            int4 x2 = __ldcs(grow + 2 * 32 + lane);
            int4 x3 = __ldcs(grow + 3 * 32 + lane);
            float4 fa = __ldcs(frow + 2 * lane);
            float4 fb = __ldcs(frow + 2 * lane + 1);

            int deg = 0;
            #pragma unroll
            for (int cc = 0; cc < 4; cc++) {
                int4 x = (cc == 0) ? x0 : (cc == 1) ? x1 : (cc == 2) ? x2 : x3;
                int w0 = 128 * cc + 4 * lane;
                unsigned m0 = __ballot_sync(0xffffffffu, (x.x != 0) || (w0     == v));
                unsigned m1 = __ballot_sync(0xffffffffu, (x.y != 0) || (w0 + 1 == v));
                unsigned m2 = __ballot_sync(0xffffffffu, (x.z != 0) || (w0 + 2 == v));
                unsigned m3 = __ballot_sync(0xffffffffu, (x.w != 0) || (w0 + 3 == v));
                deg += __popc(m0) + __popc(m1) + __popc(m2) + __popc(m3);
                if (lane == cc) {
                    ((uint4*)g_bits)[(size_t)row * 4 + cc] = make_uint4(m0, m1, m2, m3);
                }
            }

            float acc0 = fa.x * w0r[0];             float acc1 = fa.x * w1r[0];
            acc0 = fmaf(fa.y, w0r[1], acc0);        acc1 = fmaf(fa.y, w1r[1], acc1);
            acc0 = fmaf(fa.z, w0r[2], acc0);        acc1 = fmaf(fa.z, w1r[2], acc1);
            acc0 = fmaf(fa.w, w0r[3], acc0);        acc1 = fmaf(fa.w, w1r[3], acc1);
            acc0 = fmaf(fb.x, w0r[4], acc0);        acc1 = fmaf(fb.x, w1r[4], acc1);
            acc0 = fmaf(fb.y, w0r[5], acc0);        acc1 = fmaf(fb.y, w1r[5], acc1);
            acc0 = fmaf(fb.z, w0r[6], acc0);        acc1 = fmaf(fb.z, w1r[6], acc1);
            acc0 = fmaf(fb.w, w0r[7], acc0);        acc1 = fmaf(fb.w, w1r[7], acc1);
            #pragma unroll
            for (int s = 16; s; s >>= 1) {
                acc0 += __shfl_xor_sync(0xffffffffu, acc0, s);
                acc1 += __shfl_xor_sync(0xffffffffu, acc1, s);
            }
            if (lane == 0) {
                float d = rsqrtf((float)deg);        // deg >= 1 (self-loop)
                g_dinv[row] = d;
                g_sxw[row]  = make_float2(d * acc0, d * acc1);
            }
        }

        // publish: all 4 rows of this chunk are complete
        __syncwarp();
        if (lane == 0) {
            __threadfence();                          // release
            atomicAdd(&g_counter[batch_of], ROWS_PER_CHUNK);
        }
    }
}

extern "C" void kernel_launch(void* const* d_in, const int* in_sizes, int n_in,
                              void* d_out, int out_size) {
    const float* features    = (const float*)d_in[0];
    const int*   graphs      = (const int*)  d_in[1];
    const float* conv_weight = (const float*)d_in[2];
    const float* conv_bias   = (const float*)d_in[3];
    const float* lin_weight  = (const float*)d_in[4];
    const float* lin_bias    = (const float*)d_in[5];
    float* out = (float*)d_out;

    init_kernel<<<1, BATCH + 32>>>();
    gcn_fused_kernel<<<GRID, NTHREADS>>>(features, graphs, conv_weight,
                                         conv_bias, lin_weight, lin_bias, out);
}